// round 10
// baseline (speedup 1.0000x reference)
#include <cuda_runtime.h>
#include <cuda_bf16.h>
#include <math.h>
#include <stdint.h>

#define D_MODEL 2048
#define T_SEQ   2048
#define NQH     32
#define NKVH    8
#define HD      64
#define DIM_KV  512
#define KDIM    2048
#define K2DIM   (3*KDIM)        // split-bf16 expanded K = 6144
#define PADH    72              // GEMM smem row stride (halves)
#define FPAD    200             // flash Q/K smem row stride (halves)
#define VPAD    136             // flash V smem row stride (halves)

// ---------------------------------------------------------------------------
// Device-global scratch
// ---------------------------------------------------------------------------
__device__ float g_Q[T_SEQ * D_MODEL];
__device__ float g_K[T_SEQ * DIM_KV];
__device__ float g_V[T_SEQ * DIM_KV];
__device__ float g_O[T_SEQ * D_MODEL];
__device__ __align__(16) __nv_bfloat16 g_A2q[T_SEQ * K2DIM];
__device__ __align__(16) __nv_bfloat16 g_A2k[T_SEQ * K2DIM];
__device__ __align__(16) __nv_bfloat16 g_A2v[T_SEQ * K2DIM];
__device__ __align__(16) __nv_bfloat16 g_A2o[T_SEQ * K2DIM];
__device__ __align__(16) __nv_bfloat16 g_B2q[D_MODEL * K2DIM];
__device__ __align__(16) __nv_bfloat16 g_B2k[DIM_KV  * K2DIM];
__device__ __align__(16) __nv_bfloat16 g_B2v[DIM_KV  * K2DIM];
__device__ __align__(16) __nv_bfloat16 g_B2o[D_MODEL * K2DIM];
__device__ __align__(16) __nv_bfloat16 g_Q2[NQH  * T_SEQ * 192];
__device__ __align__(16) __nv_bfloat16 g_K2[NKVH * T_SEQ * 192];
__device__ __align__(16) __nv_bfloat16 g_Vth[DIM_KV * T_SEQ];
__device__ __align__(16) __nv_bfloat16 g_Vtl[DIM_KV * T_SEQ];
__device__ float g_rc[T_SEQ * 32];
__device__ float g_rs[T_SEQ * 32];

// ---------------------------------------------------------------------------
// PTX helpers (sm_80-portable only)
// ---------------------------------------------------------------------------
__device__ __forceinline__ uint32_t smem_u32(const void* p) {
    uint32_t a;
    asm("{ .reg .u64 t; cvta.to.shared.u64 t, %1; cvt.u32.u64 %0, t; }"
        : "=r"(a) : "l"(p));
    return a;
}

__device__ __forceinline__ void ldmatrix_x4(uint32_t& r0, uint32_t& r1,
                                            uint32_t& r2, uint32_t& r3,
                                            uint32_t addr) {
    asm volatile("ldmatrix.sync.aligned.m8n8.x4.shared.b16 {%0,%1,%2,%3}, [%4];"
                 : "=r"(r0), "=r"(r1), "=r"(r2), "=r"(r3) : "r"(addr));
}

__device__ __forceinline__ void mma16816(float* d, const uint32_t* a,
                                         uint32_t b0, uint32_t b1) {
    asm volatile(
        "mma.sync.aligned.m16n8k16.row.col.f32.bf16.bf16.f32 "
        "{%0,%1,%2,%3}, {%4,%5,%6,%7}, {%8,%9}, {%0,%1,%2,%3};"
        : "+f"(d[0]), "+f"(d[1]), "+f"(d[2]), "+f"(d[3])
        : "r"(a[0]), "r"(a[1]), "r"(a[2]), "r"(a[3]), "r"(b0), "r"(b1));
}

__device__ __forceinline__ void cp_async16(uint32_t saddr, const void* gaddr) {
    asm volatile("cp.async.cg.shared.global [%0], [%1], 16;"
                 :: "r"(saddr), "l"(gaddr));
}
#define CP_COMMIT() asm volatile("cp.async.commit_group;" ::: "memory")
#define CP_WAIT(n)  asm volatile("cp.async.wait_group %0;" :: "n"(n) : "memory")

__device__ __forceinline__ uint32_t pack_bf16x2(float a, float b) {
    uint32_t r;
    asm("cvt.rn.bf16x2.f32 %0, %1, %2;" : "=r"(r) : "f"(b), "f"(a));
    return r;
}

// ---------------------------------------------------------------------------
// Split-bf16 conversions for the projection GEMMs
// ---------------------------------------------------------------------------
__global__ void split_a_kernel(const float* __restrict__ X,
                               __nv_bfloat16* __restrict__ A2, int M)
{
    int idx = blockIdx.x * blockDim.x + threadIdx.x;
    if (idx >= M * KDIM) return;
    int m = idx / KDIM, k = idx % KDIM;
    float x = X[idx];
    __nv_bfloat16 h = __float2bfloat16(x);
    __nv_bfloat16 l = __float2bfloat16(x - __bfloat162float(h));
    size_t b = (size_t)m * K2DIM;
    A2[b + k]            = h;
    A2[b + KDIM + k]     = l;
    A2[b + 2 * KDIM + k] = h;
}

__global__ void split_b_kernel(const float* __restrict__ W,
                               __nv_bfloat16* __restrict__ B2, int N)
{
    __shared__ float tile[32][33];
    int n0 = blockIdx.x * 32, k0 = blockIdx.y * 32;
    int tx = threadIdx.x, ty = threadIdx.y;
    #pragma unroll
    for (int i = 0; i < 32; i += 8)
        tile[ty + i][tx] = W[(size_t)(k0 + ty + i) * N + n0 + tx];
    __syncthreads();
    #pragma unroll
    for (int i = 0; i < 32; i += 8) {
        int n = n0 + ty + i;
        float x = tile[tx][ty + i];
        __nv_bfloat16 h = __float2bfloat16(x);
        __nv_bfloat16 l = __float2bfloat16(x - __bfloat162float(h));
        size_t b = (size_t)n * K2DIM;
        B2[b + k0 + tx]            = h;
        B2[b + KDIM + k0 + tx]     = h;
        B2[b + 2 * KDIM + k0 + tx] = l;
    }
}

// ---------------------------------------------------------------------------
// HMMA GEMM: C[M,N] = A2[M,3K] @ B2[N,3K]^T.
// CTA tile 256x128, 256 threads = 8 warps (4x2), warp tile 64x64.
// 3-stage cp.async pipeline, distance-2 prefetch. 1 CTA/SM.
// ---------------------------------------------------------------------------
#define GSTG_A   (256 * PADH * 2)                 // 36864 bytes
#define GSTG     ((256 + 128) * PADH * 2)         // 55296 bytes
#define GEMM_SMEM_BYTES (3 * GSTG)                // 165888 bytes

__global__ __launch_bounds__(256, 1) void gemm_hmma_kernel(
    const __nv_bfloat16* __restrict__ A2, const __nv_bfloat16* __restrict__ B2,
    float* __restrict__ C, int N)
{
    extern __shared__ __nv_bfloat16 sh[];
    const uint32_t shBase = smem_u32(sh);

    const int tid  = threadIdx.x;
    const int lane = tid & 31;
    const int wid  = tid >> 5;     // 0..7
    const int wm   = wid & 3;      // m offset 0/64/128/192
    const int wn   = wid >> 2;     // n offset 0/64

    const int rowBase = blockIdx.y * 256;
    const int colBase = blockIdx.x * 128;
    const __nv_bfloat16* Ag = A2 + (size_t)rowBase * K2DIM;
    const __nv_bfloat16* Bg = B2 + (size_t)colBase * K2DIM;

    float acc[4][8][4];
    #pragma unroll
    for (int i = 0; i < 4; i++)
        #pragma unroll
        for (int j = 0; j < 8; j++)
            #pragma unroll
            for (int q = 0; q < 4; q++) acc[i][j][q] = 0.0f;

    const int nCh = K2DIM / 64;    // 96

    // stage loader: A 256x64 halves (2048 chunks), B 128x64 (1024 chunks)
    auto load_stage = [&](int st, int k0) {
        const uint32_t sA = shBase + st * GSTG;
        const uint32_t sB = sA + GSTG_A;
        #pragma unroll
        for (int i = 0; i < 8; i++) {
            int id  = tid + (i << 8);
            int row = id >> 3;
            int c8  = id & 7;
            cp_async16(sA + (uint32_t)(row * PADH + c8 * 8) * 2,
                       Ag + (size_t)row * K2DIM + k0 + c8 * 8);
        }
        #pragma unroll
        for (int i = 0; i < 4; i++) {
            int id  = tid + (i << 8);
            int row = id >> 3;
            int c8  = id & 7;
            cp_async16(sB + (uint32_t)(row * PADH + c8 * 8) * 2,
                       Bg + (size_t)row * K2DIM + k0 + c8 * 8);
        }
        CP_COMMIT();
    };

    load_stage(0, 0);
    load_stage(1, 64);

    const int lrow = (lane & 7) + ((lane >> 3) & 1) * 8;
    const int lcol = (lane >> 4) * 8;

    int s = 0;   // stage of current chunk
    for (int c = 0; c < nCh; c++) {
        if (c + 2 < nCh) {
            int s2 = s + 2; if (s2 >= 3) s2 -= 3;
            load_stage(s2, (c + 2) * 64);
            CP_WAIT(2);
        } else {
            CP_WAIT(0);
        }
        __syncthreads();

        const uint32_t aB = shBase + s * GSTG;
        const uint32_t bB = aB + GSTG_A;
        #pragma unroll
        for (int ks = 0; ks < 4; ks++) {
            const int k16 = ks * 16;
            uint32_t af[4][4], bfr[4][4];
            #pragma unroll
            for (int fm = 0; fm < 4; fm++)
                ldmatrix_x4(af[fm][0], af[fm][1], af[fm][2], af[fm][3],
                    aB + (uint32_t)((wm * 64 + fm * 16 + lrow) * PADH + k16 + lcol) * 2);
            #pragma unroll
            for (int fp = 0; fp < 4; fp++)
                ldmatrix_x4(bfr[fp][0], bfr[fp][1], bfr[fp][2], bfr[fp][3],
                    bB + (uint32_t)((wn * 64 + fp * 16 + lrow) * PADH + k16 + lcol) * 2);
            #pragma unroll
            for (int fm = 0; fm < 4; fm++)
                #pragma unroll
                for (int fn = 0; fn < 8; fn++) {
                    uint32_t b0 = (fn & 1) ? bfr[fn >> 1][1] : bfr[fn >> 1][0];
                    uint32_t b1 = (fn & 1) ? bfr[fn >> 1][3] : bfr[fn >> 1][2];
                    mma16816(acc[fm][fn], af[fm], b0, b1);
                }
        }
        __syncthreads();
        if (++s == 3) s = 0;
    }

    #pragma unroll
    for (int fm = 0; fm < 4; fm++) {
        #pragma unroll
        for (int fn = 0; fn < 8; fn++) {
            int r0 = rowBase + wm * 64 + fm * 16 + (lane >> 2);
            int c0 = colBase + wn * 64 + fn * 8 + (lane & 3) * 2;
            float2 v01 = make_float2(acc[fm][fn][0], acc[fm][fn][1]);
            float2 v23 = make_float2(acc[fm][fn][2], acc[fm][fn][3]);
            *reinterpret_cast<float2*>(&C[(size_t)r0 * N + c0]) = v01;
            *reinterpret_cast<float2*>(&C[(size_t)(r0 + 8) * N + c0]) = v23;
        }
    }
}

// ---------------------------------------------------------------------------
// RoPE
// ---------------------------------------------------------------------------
__global__ void rope_table_kernel(float* __restrict__ rc, float* __restrict__ rs)
{
    int idx = blockIdx.x * blockDim.x + threadIdx.x;
    if (idx >= T_SEQ * 32) return;
    int t = idx >> 5, i = idx & 31;
    float invf = (float)pow(500000.0, -(double)i / 32.0);
    float angf = (float)t * invf;
    double ang = (double)angf;
    rc[idx] = (float)cos(ang);
    rs[idx] = (float)sin(ang);
}

__global__ void rope_kernel(float* __restrict__ X,
                            const float* __restrict__ rc,
                            const float* __restrict__ rs,
                            int nheads, int rowstride)
{
    int idx = blockIdx.x * blockDim.x + threadIdx.x;
    int total = T_SEQ * nheads * 32;
    if (idx >= total) return;
    int i  = idx & 31;
    int tmp = idx >> 5;
    int h  = tmp % nheads;
    int t  = tmp / nheads;

    float c = rc[t * 32 + i];
    float s = rs[t * 32 + i];
    float* p = X + (size_t)t * rowstride + h * HD + 2 * i;
    float x1 = p[0], x2 = p[1];
    p[0] = x1 * c - x2 * s;
    p[1] = x1 * s + x2 * c;
}

// ---------------------------------------------------------------------------
// Attention prep
// ---------------------------------------------------------------------------
__global__ void headsplit_kernel(const float* __restrict__ X,
                                 __nv_bfloat16* __restrict__ Y,
                                 int nheads, int rowstride, int mode)
{
    int idx = blockIdx.x * blockDim.x + threadIdx.x;
    if (idx >= nheads * T_SEQ * HD) return;
    int d = idx & 63;
    int t = (idx >> 6) & (T_SEQ - 1);
    int h = idx >> 17;
    float x = X[(size_t)t * rowstride + h * HD + d];
    __nv_bfloat16 hh = __float2bfloat16(x);
    __nv_bfloat16 ll = __float2bfloat16(x - __bfloat162float(hh));
    size_t b = ((size_t)h * T_SEQ + t) * 192;
    Y[b + d]        = hh;
    Y[b + 64 + d]   = mode ? hh : ll;
    Y[b + 128 + d]  = mode ? ll : hh;
}

__global__ void vt2split_kernel(const float* __restrict__ V,
                                __nv_bfloat16* __restrict__ Vth,
                                __nv_bfloat16* __restrict__ Vtl)
{
    __shared__ float tile[32][33];
    int d0 = blockIdx.x * 32, t0 = blockIdx.y * 32;
    int tx = threadIdx.x, ty = threadIdx.y;
    #pragma unroll
    for (int i = 0; i < 32; i += 8)
        tile[ty + i][tx] = V[(size_t)(t0 + ty + i) * DIM_KV + d0 + tx];
    __syncthreads();
    #pragma unroll
    for (int i = 0; i < 32; i += 8) {
        int d = d0 + ty + i;
        float x = tile[tx][ty + i];
        __nv_bfloat16 hh = __float2bfloat16(x);
        __nv_bfloat16 ll = __float2bfloat16(x - __bfloat162float(hh));
        Vth[(size_t)d * T_SEQ + t0 + tx] = hh;
        Vtl[(size_t)d * T_SEQ + t0 + tx] = ll;
    }
}

// ---------------------------------------------------------------------------
// HMMA flash attention (unchanged from R9)
// ---------------------------------------------------------------------------
#define FLASH_SMEM_BYTES ((128 * FPAD + 64 * FPAD + 64 * VPAD) * 2)

__global__ __launch_bounds__(128) void flash_hmma_kernel(
    const __nv_bfloat16* __restrict__ Q2,
    const __nv_bfloat16* __restrict__ K2,
    const __nv_bfloat16* __restrict__ Vth,
    const __nv_bfloat16* __restrict__ Vtl,
    float* __restrict__ O)
{
    extern __shared__ __nv_bfloat16 fs[];
    const uint32_t QsA = smem_u32(fs);
    const uint32_t KsA = QsA + 128 * FPAD * 2;
    const uint32_t VsA = KsA + 64 * FPAD * 2;

    const int tid = threadIdx.x, lane = tid & 31, wq = tid >> 5;
    const int h = blockIdx.y, kvh = h >> 2;
    const int m0 = (gridDim.x - 1 - (int)blockIdx.x) * 128;

    const int g  = lane >> 2;
    const int tg = lane & 3;
    const int lrow = (lane & 7) + ((lane >> 3) & 1) * 8;
    const int lcol = (lane >> 4) * 8;
    const float NEG = -1e30f;
    const float scale = 0.125f;

    {
        const __nv_bfloat16* Qg = Q2 + ((size_t)h * T_SEQ + m0) * 192;
        for (int id = tid; id < 3072; id += 128) {
            int row = id / 24, c = id - row * 24;
            cp_async16(QsA + (uint32_t)(row * FPAD + c * 8) * 2,
                       Qg + (size_t)row * 192 + c * 8);
        }
        CP_COMMIT();
    }

    float o[2][8][4];
    #pragma unroll
    for (int i = 0; i < 2; i++)
        #pragma unroll
        for (int j = 0; j < 8; j++)
            #pragma unroll
            for (int q = 0; q < 4; q++) o[i][j][q] = 0.0f;
    float mrow[2][2] = {{NEG, NEG}, {NEG, NEG}};
    float lacc[2][2] = {{0.f, 0.f}, {0.f, 0.f}};

    const int nT = m0 / 64 + 2;
    for (int jt = 0; jt < nT; jt++) {
        const int j0 = jt * 64;
        __syncthreads();
        for (int id = tid; id < 1536; id += 128) {
            int row = id / 24, c = id - row * 24;
            cp_async16(KsA + (uint32_t)(row * FPAD + c * 8) * 2,
                       K2 + ((size_t)kvh * T_SEQ + j0 + row) * 192 + c * 8);
        }
        for (int id = tid; id < 1024; id += 128) {
            int row = id >> 4, c = id & 15;
            const __nv_bfloat16* src = (c < 8)
                ? Vth + (size_t)(kvh * 64 + row) * T_SEQ + j0 + c * 8
                : Vtl + (size_t)(kvh * 64 + row) * T_SEQ + j0 + (c - 8) * 8;
            cp_async16(VsA + (uint32_t)(row * VPAD + c * 8) * 2, src);
        }
        CP_COMMIT();
        CP_WAIT(0);
        __syncthreads();

        float s[2][8][4];
        #pragma unroll
        for (int i = 0; i < 2; i++)
            #pragma unroll
            for (int j = 0; j < 8; j++)
                #pragma unroll
                for (int q = 0; q < 4; q++) s[i][j][q] = 0.0f;

        #pragma unroll
        for (int kc = 0; kc < 12; kc++) {
            uint32_t af[2][4], bk[4][4];
            #pragma unroll
            for (int fm = 0; fm < 2; fm++)
                ldmatrix_x4(af[fm][0], af[fm][1], af[fm][2], af[fm][3],
                    QsA + (uint32_t)((wq * 32 + fm * 16 + lrow) * FPAD + kc * 16 + lcol) * 2);
            #pragma unroll
            for (int fp = 0; fp < 4; fp++)
                ldmatrix_x4(bk[fp][0], bk[fp][1], bk[fp][2], bk[fp][3],
                    KsA + (uint32_t)((fp * 16 + lrow) * FPAD + kc * 16 + lcol) * 2);
            #pragma unroll
            for (int fm = 0; fm < 2; fm++)
                #pragma unroll
                for (int fn = 0; fn < 8; fn++) {
                    uint32_t b0 = (fn & 1) ? bk[fn >> 1][1] : bk[fn >> 1][0];
                    uint32_t b1 = (fn & 1) ? bk[fn >> 1][3] : bk[fn >> 1][2];
                    mma16816(s[fm][fn], af[fm], b0, b1);
                }
        }

        #pragma unroll
        for (int fm = 0; fm < 2; fm++) {
            const int r0 = m0 + wq * 32 + fm * 16 + g;
            const int r1 = r0 + 8;
            float mx0 = NEG, mx1 = NEG;
            #pragma unroll
            for (int fn = 0; fn < 8; fn++) {
                const int cb = j0 + fn * 8 + tg * 2;
                float v0 = (cb     <= r0) ? s[fm][fn][0] * scale : NEG;
                float v1 = (cb + 1 <= r0) ? s[fm][fn][1] * scale : NEG;
                float v2 = (cb     <= r1) ? s[fm][fn][2] * scale : NEG;
                float v3 = (cb + 1 <= r1) ? s[fm][fn][3] * scale : NEG;
                s[fm][fn][0] = v0; s[fm][fn][1] = v1;
                s[fm][fn][2] = v2; s[fm][fn][3] = v3;
                mx0 = fmaxf(mx0, fmaxf(v0, v1));
                mx1 = fmaxf(mx1, fmaxf(v2, v3));
            }
            mx0 = fmaxf(mx0, __shfl_xor_sync(0xffffffffu, mx0, 1));
            mx0 = fmaxf(mx0, __shfl_xor_sync(0xffffffffu, mx0, 2));
            mx1 = fmaxf(mx1, __shfl_xor_sync(0xffffffffu, mx1, 1));
            mx1 = fmaxf(mx1, __shfl_xor_sync(0xffffffffu, mx1, 2));
            const float mn0 = fmaxf(mrow[fm][0], mx0);
            const float mn1 = fmaxf(mrow[fm][1], mx1);
            const float c0 = __expf(mrow[fm][0] - mn0);
            const float c1 = __expf(mrow[fm][1] - mn1);
            mrow[fm][0] = mn0; mrow[fm][1] = mn1;
            float ls0 = 0.f, ls1 = 0.f;
            #pragma unroll
            for (int fn = 0; fn < 8; fn++) {
                float p0 = __expf(s[fm][fn][0] - mn0);
                float p1 = __expf(s[fm][fn][1] - mn0);
                float p2 = __expf(s[fm][fn][2] - mn1);
                float p3 = __expf(s[fm][fn][3] - mn1);
                s[fm][fn][0] = p0; s[fm][fn][1] = p1;
                s[fm][fn][2] = p2; s[fm][fn][3] = p3;
                ls0 += p0 + p1; ls1 += p2 + p3;
                o[fm][fn][0] *= c0; o[fm][fn][1] *= c0;
                o[fm][fn][2] *= c1; o[fm][fn][3] *= c1;
            }
            lacc[fm][0] = lacc[fm][0] * c0 + ls0;
            lacc[fm][1] = lacc[fm][1] * c1 + ls1;
        }

        #pragma unroll
        for (int kc2 = 0; kc2 < 4; kc2++) {
            uint32_t aPh[2][4], aPl[2][4];
            #pragma unroll
            for (int fm = 0; fm < 2; fm++) {
                #pragma unroll
                for (int half = 0; half < 2; half++) {
                    const int fr = 2 * kc2 + half;
                    float p0 = s[fm][fr][0], p1 = s[fm][fr][1];
                    float p2 = s[fm][fr][2], p3 = s[fm][fr][3];
                    __nv_bfloat16 h0 = __float2bfloat16(p0), h1 = __float2bfloat16(p1);
                    __nv_bfloat16 h2 = __float2bfloat16(p2), h3 = __float2bfloat16(p3);
                    aPh[fm][half * 2 + 0] =
                        ((uint32_t)__bfloat16_as_ushort(h1) << 16) | __bfloat16_as_ushort(h0);
                    aPh[fm][half * 2 + 1] =
                        ((uint32_t)__bfloat16_as_ushort(h3) << 16) | __bfloat16_as_ushort(h2);
                    aPl[fm][half * 2 + 0] = pack_bf16x2(p0 - __bfloat162float(h0),
                                                        p1 - __bfloat162float(h1));
                    aPl[fm][half * 2 + 1] = pack_bf16x2(p2 - __bfloat162float(h2),
                                                        p3 - __bfloat162float(h3));
                }
            }

            uint32_t bv[4][4];
            #pragma unroll
            for (int fp = 0; fp < 4; fp++)
                ldmatrix_x4(bv[fp][0], bv[fp][1], bv[fp][2], bv[fp][3],
                    VsA + (uint32_t)((fp * 16 + lrow) * VPAD + kc2 * 16 + lcol) * 2);
            #pragma unroll
            for (int fm = 0; fm < 2; fm++)
                #pragma unroll
                for (int fn = 0; fn < 8; fn++) {
                    uint32_t b0 = (fn & 1) ? bv[fn >> 1][1] : bv[fn >> 1][0];
                    uint32_t b1 = (fn & 1) ? bv[fn >> 1][3] : bv[fn >> 1][2];
                    mma16816(o[fm][fn], aPh[fm], b0, b1);
                    mma16816(o[fm][fn], aPl[fm], b0, b1);
                }
            #pragma unroll
            for (int fp = 0; fp < 4; fp++)
                ldmatrix_x4(bv[fp][0], bv[fp][1], bv[fp][2], bv[fp][3],
                    VsA + (uint32_t)((fp * 16 + lrow) * VPAD + 64 + kc2 * 16 + lcol) * 2);
            #pragma unroll
            for (int fm = 0; fm < 2; fm++)
                #pragma unroll
                for (int fn = 0; fn < 8; fn++) {
                    uint32_t b0 = (fn & 1) ? bv[fn >> 1][1] : bv[fn >> 1][0];
                    uint32_t b1 = (fn & 1) ? bv[fn >> 1][3] : bv[fn >> 1][2];
                    mma16816(o[fm][fn], aPh[fm], b0, b1);
                }
        }
    }

    float linv[2][2];
    #pragma unroll
    for (int fm = 0; fm < 2; fm++)
        #pragma unroll
        for (int half = 0; half < 2; half++) {
            float lv = lacc[fm][half];
            lv += __shfl_xor_sync(0xffffffffu, lv, 1);
            lv += __shfl_xor_sync(0xffffffffu, lv, 2);
            linv[fm][half] = 1.0f / lv;
        }
    #pragma unroll
    for (int fm = 0; fm < 2; fm++) {
        const int r0 = m0 + wq * 32 + fm * 16 + g;
        #pragma unroll
        for (int fn = 0; fn < 8; fn++) {
            const int c0 = h * HD + fn * 8 + tg * 2;
            float2 v01 = make_float2(o[fm][fn][0] * linv[fm][0],
                                     o[fm][fn][1] * linv[fm][0]);
            float2 v23 = make_float2(o[fm][fn][2] * linv[fm][1],
                                     o[fm][fn][3] * linv[fm][1]);
            *reinterpret_cast<float2*>(&O[(size_t)r0 * D_MODEL + c0]) = v01;
            *reinterpret_cast<float2*>(&O[(size_t)(r0 + 8) * D_MODEL + c0]) = v23;
        }
    }
}

// ---------------------------------------------------------------------------
// Launch
// ---------------------------------------------------------------------------
extern "C" void kernel_launch(void* const* d_in, const int* in_sizes, int n_in,
                              void* d_out, int out_size)
{
    const float *q_embs, *k_embs, *v_embs, *w_q, *w_k, *w_v, *w_o;
    if (in_sizes[3] == D_MODEL * DIM_KV) {
        k_embs = (const float*)d_in[0];
        q_embs = (const float*)d_in[1];
        v_embs = (const float*)d_in[2];
        w_k    = (const float*)d_in[3];
        w_o    = (const float*)d_in[4];
        w_q    = (const float*)d_in[5];
        w_v    = (const float*)d_in[6];
    } else {
        q_embs = (const float*)d_in[0];
        k_embs = (const float*)d_in[1];
        v_embs = (const float*)d_in[2];
        w_q    = (const float*)d_in[3];
        w_k    = (const float*)d_in[4];
        w_v    = (const float*)d_in[5];
        w_o    = (const float*)d_in[6];
    }
    float* out = (float*)d_out;

    float *Q, *K, *V, *O, *RC, *RS;
    __nv_bfloat16 *A2q, *A2k, *A2v, *A2o, *B2q, *B2k, *B2v, *B2o;
    __nv_bfloat16 *Q2, *K2, *Vth, *Vtl;
    cudaGetSymbolAddress((void**)&Q,   g_Q);
    cudaGetSymbolAddress((void**)&K,   g_K);
    cudaGetSymbolAddress((void**)&V,   g_V);
    cudaGetSymbolAddress((void**)&O,   g_O);
    cudaGetSymbolAddress((void**)&A2q, g_A2q);
    cudaGetSymbolAddress((void**)&A2k, g_A2k);
    cudaGetSymbolAddress((void**)&A2v, g_A2v);
    cudaGetSymbolAddress((void**)&A2o, g_A2o);
    cudaGetSymbolAddress((void**)&B2q, g_B2q);
    cudaGetSymbolAddress((void**)&B2k, g_B2k);
    cudaGetSymbolAddress((void**)&B2v, g_B2v);
    cudaGetSymbolAddress((void**)&B2o, g_B2o);
    cudaGetSymbolAddress((void**)&Q2,  g_Q2);
    cudaGetSymbolAddress((void**)&K2,  g_K2);
    cudaGetSymbolAddress((void**)&Vth, g_Vth);
    cudaGetSymbolAddress((void**)&Vtl, g_Vtl);
    cudaGetSymbolAddress((void**)&RC,  g_rc);
    cudaGetSymbolAddress((void**)&RS,  g_rs);

    cudaFuncSetAttribute(gemm_hmma_kernel,
                         cudaFuncAttributeMaxDynamicSharedMemorySize,
                         GEMM_SMEM_BYTES);
    cudaFuncSetAttribute(flash_hmma_kernel,
                         cudaFuncAttributeMaxDynamicSharedMemorySize,
                         FLASH_SMEM_BYTES);

    const int M = T_SEQ;
    const int convA_blocks = (M * KDIM + 255) / 256;

    split_a_kernel<<<convA_blocks, 256>>>(q_embs, A2q, M);                               // 1
    split_b_kernel<<<dim3(D_MODEL / 32, KDIM / 32), dim3(32, 8)>>>(w_q, B2q, D_MODEL);   // 2
    split_a_kernel<<<convA_blocks, 256>>>(k_embs, A2k, M);                               // 3
    gemm_hmma_kernel<<<dim3(D_MODEL / 128, M / 256), 256, GEMM_SMEM_BYTES>>>(A2q, B2q, Q, D_MODEL); // 4 (profile slot)
    split_b_kernel<<<dim3(DIM_KV / 32, KDIM / 32), dim3(32, 8)>>>(w_k, B2k, DIM_KV);     // 5
    gemm_hmma_kernel<<<dim3(DIM_KV / 128, M / 256), 256, GEMM_SMEM_BYTES>>>(A2k, B2k, K, DIM_KV);   // 6
    split_a_kernel<<<convA_blocks, 256>>>(v_embs, A2v, M);                               // 7
    split_b_kernel<<<dim3(DIM_KV / 32, KDIM / 32), dim3(32, 8)>>>(w_v, B2v, DIM_KV);     // 8
    gemm_hmma_kernel<<<dim3(DIM_KV / 128, M / 256), 256, GEMM_SMEM_BYTES>>>(A2v, B2v, V, DIM_KV);   // 9

    rope_table_kernel<<<(T_SEQ * 32 + 255) / 256, 256>>>(RC, RS);
    rope_kernel<<<(T_SEQ * NQH * 32 + 255) / 256, 256>>>(Q, RC, RS, NQH, D_MODEL);
    rope_kernel<<<(T_SEQ * NKVH * 32 + 255) / 256, 256>>>(K, RC, RS, NKVH, DIM_KV);

    headsplit_kernel<<<(NQH * T_SEQ * HD + 255) / 256, 256>>>(Q, Q2, NQH, D_MODEL, 0);
    headsplit_kernel<<<(NKVH * T_SEQ * HD + 255) / 256, 256>>>(K, K2, NKVH, DIM_KV, 1);
    vt2split_kernel<<<dim3(DIM_KV / 32, T_SEQ / 32), dim3(32, 8)>>>(V, Vth, Vtl);

    flash_hmma_kernel<<<dim3(T_SEQ / 128, NQH), 128, FLASH_SMEM_BYTES>>>(Q2, K2, Vth, Vtl, O);

    split_a_kernel<<<convA_blocks, 256>>>(O, A2o, M);
    split_b_kernel<<<dim3(D_MODEL / 32, KDIM / 32), dim3(32, 8)>>>(w_o, B2o, D_MODEL);
    gemm_hmma_kernel<<<dim3(D_MODEL / 128, M / 256), 256, GEMM_SMEM_BYTES>>>(A2o, B2o, out, D_MODEL);
}

// round 11
// speedup vs baseline: 1.6819x; 1.6819x over previous
#include <cuda_runtime.h>
#include <cuda_bf16.h>
#include <cuda_fp16.h>
#include <math.h>
#include <stdint.h>

#define D_MODEL 2048
#define T_SEQ   2048
#define NQH     32
#define NKVH    8
#define HD      64
#define DIM_KV  512
#define KDIM    2048
#define KA2     (2*KDIM)       // fp16 2-term A width = 4096
#define PADH    72             // GEMM smem row stride (halves)
#define QPAD    136            // flash Q smem row stride (halves), 272B
#define KVPAD   72             // flash K/V smem row stride (halves), 144B

// ---------------------------------------------------------------------------
// Device-global scratch
// ---------------------------------------------------------------------------
__device__ float g_V[T_SEQ * DIM_KV];
__device__ __align__(16) __half g_A2q[T_SEQ * KA2];
__device__ __align__(16) __half g_A2k[T_SEQ * KA2];
__device__ __align__(16) __half g_A2v[T_SEQ * KA2];
__device__ __align__(16) __half g_A2o[T_SEQ * KA2];      // flash output [Oh|Ol]
__device__ __align__(16) __half g_B2q[D_MODEL * KDIM];   // hi-only weights^T
__device__ __align__(16) __half g_B2k[DIM_KV  * KDIM];
__device__ __align__(16) __half g_B2v[DIM_KV  * KDIM];
__device__ __align__(16) __half g_B2o[D_MODEL * KDIM];
__device__ __align__(16) __half g_Q2[NQH  * T_SEQ * 128]; // [h][t][Qh|Ql]
__device__ __align__(16) __half g_K2h[NKVH * T_SEQ * 64]; // [kvh][t][Kh]
__device__ __align__(16) __half g_Vth[DIM_KV * T_SEQ];    // V^T hi [d][t]
__device__ float g_rc[T_SEQ * 32];
__device__ float g_rs[T_SEQ * 32];

// ---------------------------------------------------------------------------
// PTX helpers (sm_80-portable)
// ---------------------------------------------------------------------------
__device__ __forceinline__ uint32_t smem_u32(const void* p) {
    uint32_t a;
    asm("{ .reg .u64 t; cvta.to.shared.u64 t, %1; cvt.u32.u64 %0, t; }"
        : "=r"(a) : "l"(p));
    return a;
}

__device__ __forceinline__ void ldmatrix_x4(uint32_t& r0, uint32_t& r1,
                                            uint32_t& r2, uint32_t& r3,
                                            uint32_t addr) {
    asm volatile("ldmatrix.sync.aligned.m8n8.x4.shared.b16 {%0,%1,%2,%3}, [%4];"
                 : "=r"(r0), "=r"(r1), "=r"(r2), "=r"(r3) : "r"(addr));
}

__device__ __forceinline__ void mma16816(float* d, const uint32_t* a,
                                         uint32_t b0, uint32_t b1) {
    asm volatile(
        "mma.sync.aligned.m16n8k16.row.col.f32.f16.f16.f32 "
        "{%0,%1,%2,%3}, {%4,%5,%6,%7}, {%8,%9}, {%0,%1,%2,%3};"
        : "+f"(d[0]), "+f"(d[1]), "+f"(d[2]), "+f"(d[3])
        : "r"(a[0]), "r"(a[1]), "r"(a[2]), "r"(a[3]), "r"(b0), "r"(b1));
}

__device__ __forceinline__ void cp_async16(uint32_t saddr, const void* gaddr) {
    asm volatile("cp.async.cg.shared.global [%0], [%1], 16;"
                 :: "r"(saddr), "l"(gaddr));
}
#define CP_COMMIT() asm volatile("cp.async.commit_group;" ::: "memory")
#define CP_WAIT(n)  asm volatile("cp.async.wait_group %0;" :: "n"(n) : "memory")

__device__ __forceinline__ uint32_t pack_h2(__half a, __half b) {
    return ((uint32_t)__half_as_ushort(b) << 16) | __half_as_ushort(a);
}

// ---------------------------------------------------------------------------
// Conversions
// ---------------------------------------------------------------------------
// A split: X [M,2048] fp32 -> [Ah | Al] fp16 [M,4096]
__global__ void split_a_kernel(const float* __restrict__ X,
                               __half* __restrict__ A2, int M)
{
    int idx = blockIdx.x * blockDim.x + threadIdx.x;
    if (idx >= M * KDIM) return;
    int m = idx / KDIM, k = idx % KDIM;
    float x = X[idx];
    __half h = __float2half(x);
    __half l = __float2half(x - __half2float(h));
    size_t b = (size_t)m * KA2;
    A2[b + k]        = h;
    A2[b + KDIM + k] = l;
}

// B: W [K,N] fp32 -> W^T hi fp16 [N,K]
__global__ void split_b_kernel(const float* __restrict__ W,
                               __half* __restrict__ B2, int N)
{
    __shared__ float tile[32][33];
    int n0 = blockIdx.x * 32, k0 = blockIdx.y * 32;
    int tx = threadIdx.x, ty = threadIdx.y;
    #pragma unroll
    for (int i = 0; i < 32; i += 8)
        tile[ty + i][tx] = W[(size_t)(k0 + ty + i) * N + n0 + tx];
    __syncthreads();
    #pragma unroll
    for (int i = 0; i < 32; i += 8) {
        int n = n0 + ty + i;
        B2[(size_t)n * KDIM + k0 + tx] = __float2half(tile[tx][ty + i]);
    }
}

// V fp32 [t][512] -> V^T hi fp16 [d][t]
__global__ void vtsplit_kernel(const float* __restrict__ V,
                               __half* __restrict__ Vth)
{
    __shared__ float tile[32][33];
    int d0 = blockIdx.x * 32, t0 = blockIdx.y * 32;
    int tx = threadIdx.x, ty = threadIdx.y;
    #pragma unroll
    for (int i = 0; i < 32; i += 8)
        tile[ty + i][tx] = V[(size_t)(t0 + ty + i) * DIM_KV + d0 + tx];
    __syncthreads();
    #pragma unroll
    for (int i = 0; i < 32; i += 8) {
        int d = d0 + ty + i;
        Vth[(size_t)d * T_SEQ + t0 + tx] = __float2half(tile[tx][ty + i]);
    }
}

// RoPE table
__global__ void rope_table_kernel(float* __restrict__ rc, float* __restrict__ rs)
{
    int idx = blockIdx.x * blockDim.x + threadIdx.x;
    if (idx >= T_SEQ * 32) return;
    int t = idx >> 5, i = idx & 31;
    float invf = (float)pow(500000.0, -(double)i / 32.0);
    float angf = (float)t * invf;
    double ang = (double)angf;
    rc[idx] = (float)cos(ang);
    rs[idx] = (float)sin(ang);
}

// ---------------------------------------------------------------------------
// HMMA GEMM: C = A2[M,4096] @ (dup-B)[*,4096]^T where B chunks repeat mod 2048.
// CTA 128x128, 128 threads, 4 warps 64x64, double-buffered cp.async, 2 CTA/SM.
// MODE 0: plain fp32 store to C.
// MODE 1: rope + fp16 2-term split -> Q2 [h][t][128]
// MODE 2: rope + fp16 hi -> K2h [kvh][t][64]
// ---------------------------------------------------------------------------
#define GEMM_SMEM_BYTES (4 * 128 * PADH * 2)   // 73728

__device__ __forceinline__ void ldgsts_tileS(uint32_t sBase, const __half* G,
                                             int k0, int tid, int strideH)
{
    #pragma unroll
    for (int i = 0; i < 8; i++) {
        int id  = tid + (i << 7);
        int row = id >> 3;
        int c8  = id & 7;
        cp_async16(sBase + (uint32_t)(row * PADH + c8 * 8) * 2,
                   G + (size_t)row * strideH + k0 + c8 * 8);
    }
}

template<int MODE>
__global__ __launch_bounds__(128, 2) void gemm_hmma_kernel(
    const __half* __restrict__ A2, const __half* __restrict__ B2,
    float* __restrict__ C, __half* __restrict__ D2, int N,
    const float* __restrict__ rc, const float* __restrict__ rs)
{
    extern __shared__ __half sh[];
    uint32_t shBase = smem_u32(sh);
    const uint32_t TILE_B = 128 * PADH * 2;

    const int tid  = threadIdx.x;
    const int lane = tid & 31;
    const int wid  = tid >> 5;
    const int wm   = wid & 1;
    const int wn   = wid >> 1;

    const int rowBase = blockIdx.y * 128;
    const int colBase = blockIdx.x * 128;
    const __half* Ag = A2 + (size_t)rowBase * KA2;
    const __half* Bg = B2 + (size_t)colBase * KDIM;

    float acc[4][8][4];
    #pragma unroll
    for (int i = 0; i < 4; i++)
        #pragma unroll
        for (int j = 0; j < 8; j++)
            #pragma unroll
            for (int q = 0; q < 4; q++) acc[i][j][q] = 0.0f;

    const int nCh = KA2 / 64;   // 64

    ldgsts_tileS(shBase + 0 * TILE_B, Ag, 0, tid, KA2);
    ldgsts_tileS(shBase + 2 * TILE_B, Bg, 0, tid, KDIM);
    CP_COMMIT();

    const int lrow = (lane & 7) + ((lane >> 3) & 1) * 8;
    const int lcol = (lane >> 4) * 8;

    for (int c = 0; c < nCh; c++) {
        const int s = c & 1;
        if (c + 1 < nCh) {
            const int s2 = s ^ 1;
            ldgsts_tileS(shBase + s2 * TILE_B,       Ag, (c + 1) * 64, tid, KA2);
            ldgsts_tileS(shBase + (2 + s2) * TILE_B, Bg, (((c + 1) & 31)) * 64, tid, KDIM);
            CP_COMMIT();
            CP_WAIT(1);
        } else {
            CP_WAIT(0);
        }
        __syncthreads();

        const uint32_t aB = shBase + s * TILE_B;
        const uint32_t bB = shBase + (2 + s) * TILE_B;
        #pragma unroll
        for (int ks = 0; ks < 4; ks++) {
            const int k16 = ks * 16;
            uint32_t af[4][4], bfr[4][4];
            #pragma unroll
            for (int fm = 0; fm < 4; fm++)
                ldmatrix_x4(af[fm][0], af[fm][1], af[fm][2], af[fm][3],
                    aB + (uint32_t)((wm * 64 + fm * 16 + lrow) * PADH + k16 + lcol) * 2);
            #pragma unroll
            for (int fp = 0; fp < 4; fp++)
                ldmatrix_x4(bfr[fp][0], bfr[fp][1], bfr[fp][2], bfr[fp][3],
                    bB + (uint32_t)((wn * 64 + fp * 16 + lrow) * PADH + k16 + lcol) * 2);
            #pragma unroll
            for (int fm = 0; fm < 4; fm++)
                #pragma unroll
                for (int fn = 0; fn < 8; fn++) {
                    uint32_t b0 = (fn & 1) ? bfr[fn >> 1][1] : bfr[fn >> 1][0];
                    uint32_t b1 = (fn & 1) ? bfr[fn >> 1][3] : bfr[fn >> 1][2];
                    mma16816(acc[fm][fn], af[fm], b0, b1);
                }
        }
        __syncthreads();
    }

    // ---- epilogues ----
    #pragma unroll
    for (int fm = 0; fm < 4; fm++) {
        #pragma unroll
        for (int fn = 0; fn < 8; fn++) {
            int r0 = rowBase + wm * 64 + fm * 16 + (lane >> 2);
            int c0 = colBase + wn * 64 + fn * 8 + (lane & 3) * 2;
            float a0 = acc[fm][fn][0], a1 = acc[fm][fn][1];
            float a2 = acc[fm][fn][2], a3 = acc[fm][fn][3];
            if (MODE == 0) {
                *reinterpret_cast<float2*>(&C[(size_t)r0 * N + c0]) = make_float2(a0, a1);
                *reinterpret_cast<float2*>(&C[(size_t)(r0 + 8) * N + c0]) = make_float2(a2, a3);
            } else {
                const int h = c0 >> 6;
                const int d = c0 & 63;
                const int i = d >> 1;
                float c1 = rc[r0 * 32 + i],       s1 = rs[r0 * 32 + i];
                float c2 = rc[(r0 + 8) * 32 + i], s2 = rs[(r0 + 8) * 32 + i];
                float y0 = a0 * c1 - a1 * s1, y1 = a0 * s1 + a1 * c1;
                float y2 = a2 * c2 - a3 * s2, y3 = a2 * s2 + a3 * c2;
                __half h0 = __float2half(y0), h1 = __float2half(y1);
                __half h2 = __float2half(y2), h3 = __float2half(y3);
                if (MODE == 1) {
                    size_t b0 = ((size_t)h * T_SEQ + r0) * 128 + d;
                    size_t b8 = b0 + 8 * 128;
                    *reinterpret_cast<uint32_t*>(D2 + b0)      = pack_h2(h0, h1);
                    *reinterpret_cast<uint32_t*>(D2 + b8)      = pack_h2(h2, h3);
                    // lo terms
                    __half l0 = __float2half(y0 - __half2float(h0));
                    __half l1 = __float2half(y1 - __half2float(h1));
                    __half l2 = __float2half(y2 - __half2float(h2));
                    __half l3 = __float2half(y3 - __half2float(h3));
                    *reinterpret_cast<uint32_t*>(D2 + b0 + 64) = pack_h2(l0, l1);
                    *reinterpret_cast<uint32_t*>(D2 + b8 + 64) = pack_h2(l2, l3);
                } else {   // MODE 2: K hi-only
                    size_t b0 = ((size_t)h * T_SEQ + r0) * 64 + d;
                    size_t b8 = b0 + 8 * 64;
                    *reinterpret_cast<uint32_t*>(D2 + b0) = pack_h2(h0, h1);
                    *reinterpret_cast<uint32_t*>(D2 + b8) = pack_h2(h2, h3);
                }
            }
        }
    }
}

// ---------------------------------------------------------------------------
// HMMA flash attention, fp16 2-term. CTA = 128 q-rows x 1 head, 4 warps.
// S = [Qh|Ql]·Kh^T (K'=128); P·V = (Ph + Pl)·Vh.
// Output written directly in [Oh|Ol] split layout (A2o).
// ---------------------------------------------------------------------------
#define FLASH_SMEM_BYTES ((128 * QPAD + 64 * KVPAD + 64 * KVPAD) * 2)  // 53248

__global__ __launch_bounds__(128) void flash_hmma_kernel(
    const __half* __restrict__ Q2,
    const __half* __restrict__ K2h,
    const __half* __restrict__ Vth,
    __half* __restrict__ A2o)
{
    extern __shared__ __half fs[];
    const uint32_t QsA = smem_u32(fs);
    const uint32_t KsA = QsA + 128 * QPAD * 2;
    const uint32_t VsA = KsA + 64 * KVPAD * 2;

    const int tid = threadIdx.x, lane = tid & 31, wq = tid >> 5;
    const int h = blockIdx.y, kvh = h >> 2;
    const int m0 = (gridDim.x - 1 - (int)blockIdx.x) * 128;

    const int g  = lane >> 2;
    const int tg = lane & 3;
    const int lrow = (lane & 7) + ((lane >> 3) & 1) * 8;
    const int lcol = (lane >> 4) * 8;
    const float NEG = -1e30f;
    const float scale = 0.125f;

    {   // load Q tile: 128 rows x 128 halves
        const __half* Qg = Q2 + ((size_t)h * T_SEQ + m0) * 128;
        #pragma unroll
        for (int u = 0; u < 16; u++) {
            int id = tid + u * 128;
            int row = id >> 4, c = id & 15;
            cp_async16(QsA + (uint32_t)(row * QPAD + c * 8) * 2,
                       Qg + (size_t)row * 128 + c * 8);
        }
        CP_COMMIT();
    }

    float o[2][8][4];
    #pragma unroll
    for (int i = 0; i < 2; i++)
        #pragma unroll
        for (int j = 0; j < 8; j++)
            #pragma unroll
            for (int q = 0; q < 4; q++) o[i][j][q] = 0.0f;
    float mrow[2][2] = {{NEG, NEG}, {NEG, NEG}};
    float lacc[2][2] = {{0.f, 0.f}, {0.f, 0.f}};

    const int nT = m0 / 64 + 2;
    for (int jt = 0; jt < nT; jt++) {
        const int j0 = jt * 64;
        __syncthreads();
        #pragma unroll
        for (int u = 0; u < 4; u++) {   // K tile: 64 x 64 halves
            int id = tid + u * 128;
            int row = id >> 3, c = id & 7;
            cp_async16(KsA + (uint32_t)(row * KVPAD + c * 8) * 2,
                       K2h + ((size_t)kvh * T_SEQ + j0 + row) * 64 + c * 8);
        }
        #pragma unroll
        for (int u = 0; u < 4; u++) {   // V tile: 64 d-rows x 64 t
            int id = tid + u * 128;
            int row = id >> 3, c = id & 7;
            cp_async16(VsA + (uint32_t)(row * KVPAD + c * 8) * 2,
                       Vth + (size_t)(kvh * 64 + row) * T_SEQ + j0 + c * 8);
        }
        CP_COMMIT();
        CP_WAIT(0);
        __syncthreads();

        // ---- S = Q·K^T ----
        float s[2][8][4];
        #pragma unroll
        for (int i = 0; i < 2; i++)
            #pragma unroll
            for (int j = 0; j < 8; j++)
                #pragma unroll
                for (int q = 0; q < 4; q++) s[i][j][q] = 0.0f;

        #pragma unroll
        for (int kc = 0; kc < 8; kc++) {
            uint32_t af[2][4], bk[4][4];
            #pragma unroll
            for (int fm = 0; fm < 2; fm++)
                ldmatrix_x4(af[fm][0], af[fm][1], af[fm][2], af[fm][3],
                    QsA + (uint32_t)((wq * 32 + fm * 16 + lrow) * QPAD + kc * 16 + lcol) * 2);
            #pragma unroll
            for (int fp = 0; fp < 4; fp++)
                ldmatrix_x4(bk[fp][0], bk[fp][1], bk[fp][2], bk[fp][3],
                    KsA + (uint32_t)((fp * 16 + lrow) * KVPAD + (kc & 3) * 16 + lcol) * 2);
            #pragma unroll
            for (int fm = 0; fm < 2; fm++)
                #pragma unroll
                for (int fn = 0; fn < 8; fn++) {
                    uint32_t b0 = (fn & 1) ? bk[fn >> 1][1] : bk[fn >> 1][0];
                    uint32_t b1 = (fn & 1) ? bk[fn >> 1][3] : bk[fn >> 1][2];
                    mma16816(s[fm][fn], af[fm], b0, b1);
                }
        }

        // ---- mask + online softmax ----
        #pragma unroll
        for (int fm = 0; fm < 2; fm++) {
            const int r0 = m0 + wq * 32 + fm * 16 + g;
            const int r1 = r0 + 8;
            float mx0 = NEG, mx1 = NEG;
            #pragma unroll
            for (int fn = 0; fn < 8; fn++) {
                const int cb = j0 + fn * 8 + tg * 2;
                float v0 = (cb     <= r0) ? s[fm][fn][0] * scale : NEG;
                float v1 = (cb + 1 <= r0) ? s[fm][fn][1] * scale : NEG;
                float v2 = (cb     <= r1) ? s[fm][fn][2] * scale : NEG;
                float v3 = (cb + 1 <= r1) ? s[fm][fn][3] * scale : NEG;
                s[fm][fn][0] = v0; s[fm][fn][1] = v1;
                s[fm][fn][2] = v2; s[fm][fn][3] = v3;
                mx0 = fmaxf(mx0, fmaxf(v0, v1));
                mx1 = fmaxf(mx1, fmaxf(v2, v3));
            }
            mx0 = fmaxf(mx0, __shfl_xor_sync(0xffffffffu, mx0, 1));
            mx0 = fmaxf(mx0, __shfl_xor_sync(0xffffffffu, mx0, 2));
            mx1 = fmaxf(mx1, __shfl_xor_sync(0xffffffffu, mx1, 1));
            mx1 = fmaxf(mx1, __shfl_xor_sync(0xffffffffu, mx1, 2));
            const float mn0 = fmaxf(mrow[fm][0], mx0);
            const float mn1 = fmaxf(mrow[fm][1], mx1);
            const float c0 = __expf(mrow[fm][0] - mn0);
            const float c1 = __expf(mrow[fm][1] - mn1);
            mrow[fm][0] = mn0; mrow[fm][1] = mn1;
            float ls0 = 0.f, ls1 = 0.f;
            #pragma unroll
            for (int fn = 0; fn < 8; fn++) {
                float p0 = __expf(s[fm][fn][0] - mn0);
                float p1 = __expf(s[fm][fn][1] - mn0);
                float p2 = __expf(s[fm][fn][2] - mn1);
                float p3 = __expf(s[fm][fn][3] - mn1);
                s[fm][fn][0] = p0; s[fm][fn][1] = p1;
                s[fm][fn][2] = p2; s[fm][fn][3] = p3;
                ls0 += p0 + p1; ls1 += p2 + p3;
                o[fm][fn][0] *= c0; o[fm][fn][1] *= c0;
                o[fm][fn][2] *= c1; o[fm][fn][3] *= c1;
            }
            lacc[fm][0] = lacc[fm][0] * c0 + ls0;
            lacc[fm][1] = lacc[fm][1] * c1 + ls1;
        }

        // ---- O += (Ph + Pl)·Vh ----
        #pragma unroll
        for (int kc2 = 0; kc2 < 4; kc2++) {
            uint32_t aPh[2][4], aPl[2][4];
            #pragma unroll
            for (int fm = 0; fm < 2; fm++) {
                #pragma unroll
                for (int half = 0; half < 2; half++) {
                    const int fr = 2 * kc2 + half;
                    float p0 = s[fm][fr][0], p1 = s[fm][fr][1];
                    float p2 = s[fm][fr][2], p3 = s[fm][fr][3];
                    __half h0 = __float2half(p0), h1 = __float2half(p1);
                    __half h2 = __float2half(p2), h3 = __float2half(p3);
                    aPh[fm][half * 2 + 0] = pack_h2(h0, h1);
                    aPh[fm][half * 2 + 1] = pack_h2(h2, h3);
                    aPl[fm][half * 2 + 0] = pack_h2(
                        __float2half(p0 - __half2float(h0)),
                        __float2half(p1 - __half2float(h1)));
                    aPl[fm][half * 2 + 1] = pack_h2(
                        __float2half(p2 - __half2float(h2)),
                        __float2half(p3 - __half2float(h3)));
                }
            }
            uint32_t bv[4][4];
            #pragma unroll
            for (int fp = 0; fp < 4; fp++)
                ldmatrix_x4(bv[fp][0], bv[fp][1], bv[fp][2], bv[fp][3],
                    VsA + (uint32_t)((fp * 16 + lrow) * KVPAD + kc2 * 16 + lcol) * 2);
            #pragma unroll
            for (int fm = 0; fm < 2; fm++)
                #pragma unroll
                for (int fn = 0; fn < 8; fn++) {
                    uint32_t b0 = (fn & 1) ? bv[fn >> 1][1] : bv[fn >> 1][0];
                    uint32_t b1 = (fn & 1) ? bv[fn >> 1][3] : bv[fn >> 1][2];
                    mma16816(o[fm][fn], aPh[fm], b0, b1);
                    mma16816(o[fm][fn], aPl[fm], b0, b1);
                }
        }
    }

    // ---- finalize: write [Oh|Ol] split layout ----
    float linv[2][2];
    #pragma unroll
    for (int fm = 0; fm < 2; fm++)
        #pragma unroll
        for (int half = 0; half < 2; half++) {
            float lv = lacc[fm][half];
            lv += __shfl_xor_sync(0xffffffffu, lv, 1);
            lv += __shfl_xor_sync(0xffffffffu, lv, 2);
            linv[fm][half] = 1.0f / lv;
        }
    #pragma unroll
    for (int fm = 0; fm < 2; fm++) {
        const int r0 = m0 + wq * 32 + fm * 16 + g;
        #pragma unroll
        for (int fn = 0; fn < 8; fn++) {
            const int col = h * HD + fn * 8 + tg * 2;
            float y0 = o[fm][fn][0] * linv[fm][0];
            float y1 = o[fm][fn][1] * linv[fm][0];
            float y2 = o[fm][fn][2] * linv[fm][1];
            float y3 = o[fm][fn][3] * linv[fm][1];
            __half h0 = __float2half(y0), h1 = __float2half(y1);
            __half h2 = __float2half(y2), h3 = __float2half(y3);
            size_t b0 = (size_t)r0 * KA2 + col;
            size_t b8 = b0 + 8 * KA2;
            *reinterpret_cast<uint32_t*>(A2o + b0) = pack_h2(h0, h1);
            *reinterpret_cast<uint32_t*>(A2o + b8) = pack_h2(h2, h3);
            *reinterpret_cast<uint32_t*>(A2o + b0 + KDIM) = pack_h2(
                __float2half(y0 - __half2float(h0)),
                __float2half(y1 - __half2float(h1)));
            *reinterpret_cast<uint32_t*>(A2o + b8 + KDIM) = pack_h2(
                __float2half(y2 - __half2float(h2)),
                __float2half(y3 - __half2float(h3)));
        }
    }
}

// ---------------------------------------------------------------------------
// Launch
// ---------------------------------------------------------------------------
extern "C" void kernel_launch(void* const* d_in, const int* in_sizes, int n_in,
                              void* d_out, int out_size)
{
    const float *q_embs, *k_embs, *v_embs, *w_q, *w_k, *w_v, *w_o;
    if (in_sizes[3] == D_MODEL * DIM_KV) {
        k_embs = (const float*)d_in[0];
        q_embs = (const float*)d_in[1];
        v_embs = (const float*)d_in[2];
        w_k    = (const float*)d_in[3];
        w_o    = (const float*)d_in[4];
        w_q    = (const float*)d_in[5];
        w_v    = (const float*)d_in[6];
    } else {
        q_embs = (const float*)d_in[0];
        k_embs = (const float*)d_in[1];
        v_embs = (const float*)d_in[2];
        w_q    = (const float*)d_in[3];
        w_k    = (const float*)d_in[4];
        w_v    = (const float*)d_in[5];
        w_o    = (const float*)d_in[6];
    }
    float* out = (float*)d_out;

    float *V, *RC, *RS;
    __half *A2q, *A2k, *A2v, *A2o, *B2q, *B2k, *B2v, *B2o, *Q2, *K2h, *Vth;
    cudaGetSymbolAddress((void**)&V,   g_V);
    cudaGetSymbolAddress((void**)&A2q, g_A2q);
    cudaGetSymbolAddress((void**)&A2k, g_A2k);
    cudaGetSymbolAddress((void**)&A2v, g_A2v);
    cudaGetSymbolAddress((void**)&A2o, g_A2o);
    cudaGetSymbolAddress((void**)&B2q, g_B2q);
    cudaGetSymbolAddress((void**)&B2k, g_B2k);
    cudaGetSymbolAddress((void**)&B2v, g_B2v);
    cudaGetSymbolAddress((void**)&B2o, g_B2o);
    cudaGetSymbolAddress((void**)&Q2,  g_Q2);
    cudaGetSymbolAddress((void**)&K2h, g_K2h);
    cudaGetSymbolAddress((void**)&Vth, g_Vth);
    cudaGetSymbolAddress((void**)&RC,  g_rc);
    cudaGetSymbolAddress((void**)&RS,  g_rs);

    cudaFuncSetAttribute(gemm_hmma_kernel<0>,
                         cudaFuncAttributeMaxDynamicSharedMemorySize, GEMM_SMEM_BYTES);
    cudaFuncSetAttribute(gemm_hmma_kernel<1>,
                         cudaFuncAttributeMaxDynamicSharedMemorySize, GEMM_SMEM_BYTES);
    cudaFuncSetAttribute(gemm_hmma_kernel<2>,
                         cudaFuncAttributeMaxDynamicSharedMemorySize, GEMM_SMEM_BYTES);
    cudaFuncSetAttribute(flash_hmma_kernel,
                         cudaFuncAttributeMaxDynamicSharedMemorySize, FLASH_SMEM_BYTES);

    const int M = T_SEQ;
    const int convA_blocks = (M * KDIM + 255) / 256;

    rope_table_kernel<<<(T_SEQ * 32 + 255) / 256, 256>>>(RC, RS);                        // 1
    split_a_kernel<<<convA_blocks, 256>>>(q_embs, A2q, M);                               // 2
    split_b_kernel<<<dim3(D_MODEL / 32, KDIM / 32), dim3(32, 8)>>>(w_q, B2q, D_MODEL);   // 3
    gemm_hmma_kernel<1><<<dim3(D_MODEL / 128, M / 128), 128, GEMM_SMEM_BYTES>>>(
        A2q, B2q, nullptr, Q2, D_MODEL, RC, RS);                                         // 4 (profile slot)

    split_a_kernel<<<convA_blocks, 256>>>(k_embs, A2k, M);
    split_b_kernel<<<dim3(DIM_KV / 32, KDIM / 32), dim3(32, 8)>>>(w_k, B2k, DIM_KV);
    gemm_hmma_kernel<2><<<dim3(DIM_KV / 128, M / 128), 128, GEMM_SMEM_BYTES>>>(
        A2k, B2k, nullptr, K2h, DIM_KV, RC, RS);

    split_a_kernel<<<convA_blocks, 256>>>(v_embs, A2v, M);
    split_b_kernel<<<dim3(DIM_KV / 32, KDIM / 32), dim3(32, 8)>>>(w_v, B2v, DIM_KV);
    gemm_hmma_kernel<0><<<dim3(DIM_KV / 128, M / 128), 128, GEMM_SMEM_BYTES>>>(
        A2v, B2v, V, nullptr, DIM_KV, RC, RS);
    vtsplit_kernel<<<dim3(DIM_KV / 32, T_SEQ / 32), dim3(32, 8)>>>(V, Vth);

    flash_hmma_kernel<<<dim3(T_SEQ / 128, NQH), 128, FLASH_SMEM_BYTES>>>(
        Q2, K2h, Vth, A2o);

    split_b_kernel<<<dim3(D_MODEL / 32, KDIM / 32), dim3(32, 8)>>>(w_o, B2o, D_MODEL);
    gemm_hmma_kernel<0><<<dim3(D_MODEL / 128, M / 128), 128, GEMM_SMEM_BYTES>>>(
        A2o, B2o, out, nullptr, D_MODEL, RC, RS);
}

// round 12
// speedup vs baseline: 1.8778x; 1.1165x over previous
#include <cuda_runtime.h>
#include <cuda_bf16.h>
#include <cuda_fp16.h>
#include <math.h>
#include <stdint.h>

#define D_MODEL 2048
#define T_SEQ   2048
#define NQH     32
#define NKVH    8
#define HD      64
#define DIM_KV  512
#define KDIM    2048
#define KA2     (2*KDIM)       // fp16 2-term A width = 4096
#define PADH    72             // GEMM smem row stride (halves)
#define QPAD    136            // flash Q smem row stride (halves)
#define KVPAD   72             // flash K/V smem row stride (halves)

// ---------------------------------------------------------------------------
// Device-global scratch
// ---------------------------------------------------------------------------
__device__ __align__(16) __half g_A2q[T_SEQ * KA2];
__device__ __align__(16) __half g_A2k[T_SEQ * KA2];
__device__ __align__(16) __half g_A2v[T_SEQ * KA2];
__device__ __align__(16) __half g_A2o[T_SEQ * KA2];      // flash output [Oh|Ol]
__device__ __align__(16) __half g_B2q[D_MODEL * KDIM];   // hi-only weights^T
__device__ __align__(16) __half g_B2k[DIM_KV  * KDIM];
__device__ __align__(16) __half g_B2v[DIM_KV  * KDIM];
__device__ __align__(16) __half g_B2o[D_MODEL * KDIM];
__device__ __align__(16) __half g_Q2[NQH  * T_SEQ * 128]; // [h][t][Qh|Ql]
__device__ __align__(16) __half g_K2h[NKVH * T_SEQ * 64]; // [kvh][t][Kh]
__device__ __align__(16) __half g_Vth[DIM_KV * T_SEQ];    // V^T hi [d][t]
__device__ float g_rc[T_SEQ * 32];
__device__ float g_rs[T_SEQ * 32];

// ---------------------------------------------------------------------------
// PTX helpers (sm_80-portable)
// ---------------------------------------------------------------------------
__device__ __forceinline__ uint32_t smem_u32(const void* p) {
    uint32_t a;
    asm("{ .reg .u64 t; cvta.to.shared.u64 t, %1; cvt.u32.u64 %0, t; }"
        : "=r"(a) : "l"(p));
    return a;
}

__device__ __forceinline__ void ldmatrix_x4(uint32_t& r0, uint32_t& r1,
                                            uint32_t& r2, uint32_t& r3,
                                            uint32_t addr) {
    asm volatile("ldmatrix.sync.aligned.m8n8.x4.shared.b16 {%0,%1,%2,%3}, [%4];"
                 : "=r"(r0), "=r"(r1), "=r"(r2), "=r"(r3) : "r"(addr));
}

__device__ __forceinline__ void mma16816(float* d, const uint32_t* a,
                                         uint32_t b0, uint32_t b1) {
    asm volatile(
        "mma.sync.aligned.m16n8k16.row.col.f32.f16.f16.f32 "
        "{%0,%1,%2,%3}, {%4,%5,%6,%7}, {%8,%9}, {%0,%1,%2,%3};"
        : "+f"(d[0]), "+f"(d[1]), "+f"(d[2]), "+f"(d[3])
        : "r"(a[0]), "r"(a[1]), "r"(a[2]), "r"(a[3]), "r"(b0), "r"(b1));
}

__device__ __forceinline__ void cp_async16(uint32_t saddr, const void* gaddr) {
    asm volatile("cp.async.cg.shared.global [%0], [%1], 16;"
                 :: "r"(saddr), "l"(gaddr));
}
#define CP_COMMIT() asm volatile("cp.async.commit_group;" ::: "memory")
#define CP_WAIT(n)  asm volatile("cp.async.wait_group %0;" :: "n"(n) : "memory")

__device__ __forceinline__ uint32_t pack_h2(__half a, __half b) {
    return ((uint32_t)__half_as_ushort(b) << 16) | __half_as_ushort(a);
}

// ---------------------------------------------------------------------------
// Conversions
// ---------------------------------------------------------------------------
__global__ void split_a_kernel(const float* __restrict__ X,
                               __half* __restrict__ A2, int M)
{
    int idx = blockIdx.x * blockDim.x + threadIdx.x;
    if (idx >= M * KDIM) return;
    int m = idx / KDIM, k = idx % KDIM;
    float x = X[idx];
    __half h = __float2half(x);
    __half l = __float2half(x - __half2float(h));
    size_t b = (size_t)m * KA2;
    A2[b + k]        = h;
    A2[b + KDIM + k] = l;
}

__global__ void split_b_kernel(const float* __restrict__ W,
                               __half* __restrict__ B2, int N)
{
    __shared__ float tile[32][33];
    int n0 = blockIdx.x * 32, k0 = blockIdx.y * 32;
    int tx = threadIdx.x, ty = threadIdx.y;
    #pragma unroll
    for (int i = 0; i < 32; i += 8)
        tile[ty + i][tx] = W[(size_t)(k0 + ty + i) * N + n0 + tx];
    __syncthreads();
    #pragma unroll
    for (int i = 0; i < 32; i += 8) {
        int n = n0 + ty + i;
        B2[(size_t)n * KDIM + k0 + tx] = __float2half(tile[tx][ty + i]);
    }
}

__global__ void rope_table_kernel(float* __restrict__ rc, float* __restrict__ rs)
{
    int idx = blockIdx.x * blockDim.x + threadIdx.x;
    if (idx >= T_SEQ * 32) return;
    int t = idx >> 5, i = idx & 31;
    float invf = (float)pow(500000.0, -(double)i / 32.0);
    float angf = (float)t * invf;
    double ang = (double)angf;
    rc[idx] = (float)cos(ang);
    rs[idx] = (float)sin(ang);
}

// ---------------------------------------------------------------------------
// Shared GEMM mainloop (CTA 128x128, 128 threads, 4 warps 64x64,
// double-buffered cp.async). A is [M,4096] fp16 2-term; B chunks repeat mod 2048.
// ---------------------------------------------------------------------------
#define GEMM_SMEM_BYTES (4 * 128 * PADH * 2)   // 73728

__device__ __forceinline__ void ldgsts_tileS(uint32_t sBase, const __half* G,
                                             int k0, int tid, int strideH)
{
    #pragma unroll
    for (int i = 0; i < 8; i++) {
        int id  = tid + (i << 7);
        int row = id >> 3;
        int c8  = id & 7;
        cp_async16(sBase + (uint32_t)(row * PADH + c8 * 8) * 2,
                   G + (size_t)row * strideH + k0 + c8 * 8);
    }
}

__device__ __forceinline__ void gemm_mainloop(
    uint32_t shBase, const __half* Ag, const __half* Bg,
    int tid, int lane, int wm, int wn, float acc[4][8][4])
{
    const uint32_t TILE_B = 128 * PADH * 2;
    const int nCh = KA2 / 64;   // 64

    ldgsts_tileS(shBase + 0 * TILE_B, Ag, 0, tid, KA2);
    ldgsts_tileS(shBase + 2 * TILE_B, Bg, 0, tid, KDIM);
    CP_COMMIT();

    const int lrow = (lane & 7) + ((lane >> 3) & 1) * 8;
    const int lcol = (lane >> 4) * 8;

    for (int c = 0; c < nCh; c++) {
        const int s = c & 1;
        if (c + 1 < nCh) {
            const int s2 = s ^ 1;
            ldgsts_tileS(shBase + s2 * TILE_B,       Ag, (c + 1) * 64, tid, KA2);
            ldgsts_tileS(shBase + (2 + s2) * TILE_B, Bg, (((c + 1) & 31)) * 64, tid, KDIM);
            CP_COMMIT();
            CP_WAIT(1);
        } else {
            CP_WAIT(0);
        }
        __syncthreads();

        const uint32_t aB = shBase + s * TILE_B;
        const uint32_t bB = shBase + (2 + s) * TILE_B;
        #pragma unroll
        for (int ks = 0; ks < 4; ks++) {
            const int k16 = ks * 16;
            uint32_t af[4][4], bfr[4][4];
            #pragma unroll
            for (int fm = 0; fm < 4; fm++)
                ldmatrix_x4(af[fm][0], af[fm][1], af[fm][2], af[fm][3],
                    aB + (uint32_t)((wm * 64 + fm * 16 + lrow) * PADH + k16 + lcol) * 2);
            #pragma unroll
            for (int fp = 0; fp < 4; fp++)
                ldmatrix_x4(bfr[fp][0], bfr[fp][1], bfr[fp][2], bfr[fp][3],
                    bB + (uint32_t)((wn * 64 + fp * 16 + lrow) * PADH + k16 + lcol) * 2);
            #pragma unroll
            for (int fm = 0; fm < 4; fm++)
                #pragma unroll
                for (int fn = 0; fn < 8; fn++) {
                    uint32_t b0 = (fn & 1) ? bfr[fn >> 1][1] : bfr[fn >> 1][0];
                    uint32_t b1 = (fn & 1) ? bfr[fn >> 1][3] : bfr[fn >> 1][2];
                    mma16816(acc[fm][fn], af[fm], b0, b1);
                }
        }
        __syncthreads();
    }
}

// MODE 0: fp32 C.  MODE 1: rope + 2-term split -> Q2.
template<int MODE>
__global__ __launch_bounds__(128, 2) void gemm_hmma_kernel(
    const __half* __restrict__ A2, const __half* __restrict__ B2,
    float* __restrict__ C, __half* __restrict__ D2, int N,
    const float* __restrict__ rc, const float* __restrict__ rs)
{
    extern __shared__ __half sh[];
    uint32_t shBase = smem_u32(sh);
    const int tid  = threadIdx.x;
    const int lane = tid & 31;
    const int wid  = tid >> 5;
    const int wm   = wid & 1;
    const int wn   = wid >> 1;
    const int rowBase = blockIdx.y * 128;
    const int colBase = blockIdx.x * 128;

    float acc[4][8][4];
    #pragma unroll
    for (int i = 0; i < 4; i++)
        #pragma unroll
        for (int j = 0; j < 8; j++)
            #pragma unroll
            for (int q = 0; q < 4; q++) acc[i][j][q] = 0.0f;

    gemm_mainloop(shBase, A2 + (size_t)rowBase * KA2, B2 + (size_t)colBase * KDIM,
                  tid, lane, wm, wn, acc);

    #pragma unroll
    for (int fm = 0; fm < 4; fm++) {
        #pragma unroll
        for (int fn = 0; fn < 8; fn++) {
            int r0 = rowBase + wm * 64 + fm * 16 + (lane >> 2);
            int c0 = colBase + wn * 64 + fn * 8 + (lane & 3) * 2;
            float a0 = acc[fm][fn][0], a1 = acc[fm][fn][1];
            float a2 = acc[fm][fn][2], a3 = acc[fm][fn][3];
            if (MODE == 0) {
                *reinterpret_cast<float2*>(&C[(size_t)r0 * N + c0]) = make_float2(a0, a1);
                *reinterpret_cast<float2*>(&C[(size_t)(r0 + 8) * N + c0]) = make_float2(a2, a3);
            } else {
                const int h = c0 >> 6;
                const int d = c0 & 63;
                const int i = d >> 1;
                float c1 = rc[r0 * 32 + i],       s1 = rs[r0 * 32 + i];
                float c2 = rc[(r0 + 8) * 32 + i], s2 = rs[(r0 + 8) * 32 + i];
                float y0 = a0 * c1 - a1 * s1, y1 = a0 * s1 + a1 * c1;
                float y2 = a2 * c2 - a3 * s2, y3 = a2 * s2 + a3 * c2;
                __half h0 = __float2half(y0), h1 = __float2half(y1);
                __half h2 = __float2half(y2), h3 = __float2half(y3);
                size_t b0 = ((size_t)h * T_SEQ + r0) * 128 + d;
                size_t b8 = b0 + 8 * 128;
                *reinterpret_cast<uint32_t*>(D2 + b0)      = pack_h2(h0, h1);
                *reinterpret_cast<uint32_t*>(D2 + b8)      = pack_h2(h2, h3);
                __half l0 = __float2half(y0 - __half2float(h0));
                __half l1 = __float2half(y1 - __half2float(h1));
                __half l2 = __float2half(y2 - __half2float(h2));
                __half l3 = __float2half(y3 - __half2float(h3));
                *reinterpret_cast<uint32_t*>(D2 + b0 + 64) = pack_h2(l0, l1);
                *reinterpret_cast<uint32_t*>(D2 + b8 + 64) = pack_h2(l2, l3);
            }
        }
    }
}

// Merged K+V projection: blockIdx.z = 0 -> K (rope -> K2h), 1 -> V (-> Vth^T).
// 128 CTAs in one launch -> each gets its own SM.
__global__ __launch_bounds__(128, 2) void gemm_kv_kernel(
    const __half* __restrict__ A2k, const __half* __restrict__ B2k,
    const __half* __restrict__ A2v, const __half* __restrict__ B2v,
    __half* __restrict__ K2h, __half* __restrict__ Vth,
    const float* __restrict__ rc, const float* __restrict__ rs)
{
    extern __shared__ __half sh[];
    uint32_t shBase = smem_u32(sh);
    const int tid  = threadIdx.x;
    const int lane = tid & 31;
    const int wid  = tid >> 5;
    const int wm   = wid & 1;
    const int wn   = wid >> 1;
    const int rowBase = blockIdx.y * 128;
    const int colBase = blockIdx.x * 128;
    const int isV = blockIdx.z;

    const __half* Ag = (isV ? A2v : A2k) + (size_t)rowBase * KA2;
    const __half* Bg = (isV ? B2v : B2k) + (size_t)colBase * KDIM;

    float acc[4][8][4];
    #pragma unroll
    for (int i = 0; i < 4; i++)
        #pragma unroll
        for (int j = 0; j < 8; j++)
            #pragma unroll
            for (int q = 0; q < 4; q++) acc[i][j][q] = 0.0f;

    gemm_mainloop(shBase, Ag, Bg, tid, lane, wm, wn, acc);

    #pragma unroll
    for (int fm = 0; fm < 4; fm++) {
        #pragma unroll
        for (int fn = 0; fn < 8; fn++) {
            int r0 = rowBase + wm * 64 + fm * 16 + (lane >> 2);
            int c0 = colBase + wn * 64 + fn * 8 + (lane & 3) * 2;
            float a0 = acc[fm][fn][0], a1 = acc[fm][fn][1];
            float a2 = acc[fm][fn][2], a3 = acc[fm][fn][3];
            if (!isV) {
                const int h = c0 >> 6;
                const int d = c0 & 63;
                const int i = d >> 1;
                float c1 = rc[r0 * 32 + i],       s1 = rs[r0 * 32 + i];
                float c2 = rc[(r0 + 8) * 32 + i], s2 = rs[(r0 + 8) * 32 + i];
                float y0 = a0 * c1 - a1 * s1, y1 = a0 * s1 + a1 * c1;
                float y2 = a2 * c2 - a3 * s2, y3 = a2 * s2 + a3 * c2;
                size_t b0 = ((size_t)h * T_SEQ + r0) * 64 + d;
                size_t b8 = b0 + 8 * 64;
                *reinterpret_cast<uint32_t*>(K2h + b0) =
                    pack_h2(__float2half(y0), __float2half(y1));
                *reinterpret_cast<uint32_t*>(K2h + b8) =
                    pack_h2(__float2half(y2), __float2half(y3));
            } else {
                // V^T hi: Vth[d][t]
                Vth[(size_t)c0 * T_SEQ + r0]           = __float2half(a0);
                Vth[(size_t)(c0 + 1) * T_SEQ + r0]     = __float2half(a1);
                Vth[(size_t)c0 * T_SEQ + r0 + 8]       = __float2half(a2);
                Vth[(size_t)(c0 + 1) * T_SEQ + r0 + 8] = __float2half(a3);
            }
        }
    }
}

// ---------------------------------------------------------------------------
// HMMA flash attention (unchanged from R11)
// ---------------------------------------------------------------------------
#define FLASH_SMEM_BYTES ((128 * QPAD + 64 * KVPAD + 64 * KVPAD) * 2)

__global__ __launch_bounds__(128) void flash_hmma_kernel(
    const __half* __restrict__ Q2,
    const __half* __restrict__ K2h,
    const __half* __restrict__ Vth,
    __half* __restrict__ A2o)
{
    extern __shared__ __half fs[];
    const uint32_t QsA = smem_u32(fs);
    const uint32_t KsA = QsA + 128 * QPAD * 2;
    const uint32_t VsA = KsA + 64 * KVPAD * 2;

    const int tid = threadIdx.x, lane = tid & 31, wq = tid >> 5;
    const int h = blockIdx.y, kvh = h >> 2;
    const int m0 = (gridDim.x - 1 - (int)blockIdx.x) * 128;

    const int g  = lane >> 2;
    const int tg = lane & 3;
    const int lrow = (lane & 7) + ((lane >> 3) & 1) * 8;
    const int lcol = (lane >> 4) * 8;
    const float NEG = -1e30f;
    const float scale = 0.125f;

    {
        const __half* Qg = Q2 + ((size_t)h * T_SEQ + m0) * 128;
        #pragma unroll
        for (int u = 0; u < 16; u++) {
            int id = tid + u * 128;
            int row = id >> 4, c = id & 15;
            cp_async16(QsA + (uint32_t)(row * QPAD + c * 8) * 2,
                       Qg + (size_t)row * 128 + c * 8);
        }
        CP_COMMIT();
    }

    float o[2][8][4];
    #pragma unroll
    for (int i = 0; i < 2; i++)
        #pragma unroll
        for (int j = 0; j < 8; j++)
            #pragma unroll
            for (int q = 0; q < 4; q++) o[i][j][q] = 0.0f;
    float mrow[2][2] = {{NEG, NEG}, {NEG, NEG}};
    float lacc[2][2] = {{0.f, 0.f}, {0.f, 0.f}};

    const int nT = m0 / 64 + 2;
    for (int jt = 0; jt < nT; jt++) {
        const int j0 = jt * 64;
        __syncthreads();
        #pragma unroll
        for (int u = 0; u < 4; u++) {
            int id = tid + u * 128;
            int row = id >> 3, c = id & 7;
            cp_async16(KsA + (uint32_t)(row * KVPAD + c * 8) * 2,
                       K2h + ((size_t)kvh * T_SEQ + j0 + row) * 64 + c * 8);
        }
        #pragma unroll
        for (int u = 0; u < 4; u++) {
            int id = tid + u * 128;
            int row = id >> 3, c = id & 7;
            cp_async16(VsA + (uint32_t)(row * KVPAD + c * 8) * 2,
                       Vth + (size_t)(kvh * 64 + row) * T_SEQ + j0 + c * 8);
        }
        CP_COMMIT();
        CP_WAIT(0);
        __syncthreads();

        float s[2][8][4];
        #pragma unroll
        for (int i = 0; i < 2; i++)
            #pragma unroll
            for (int j = 0; j < 8; j++)
                #pragma unroll
                for (int q = 0; q < 4; q++) s[i][j][q] = 0.0f;

        #pragma unroll
        for (int kc = 0; kc < 8; kc++) {
            uint32_t af[2][4], bk[4][4];
            #pragma unroll
            for (int fm = 0; fm < 2; fm++)
                ldmatrix_x4(af[fm][0], af[fm][1], af[fm][2], af[fm][3],
                    QsA + (uint32_t)((wq * 32 + fm * 16 + lrow) * QPAD + kc * 16 + lcol) * 2);
            #pragma unroll
            for (int fp = 0; fp < 4; fp++)
                ldmatrix_x4(bk[fp][0], bk[fp][1], bk[fp][2], bk[fp][3],
                    KsA + (uint32_t)((fp * 16 + lrow) * KVPAD + (kc & 3) * 16 + lcol) * 2);
            #pragma unroll
            for (int fm = 0; fm < 2; fm++)
                #pragma unroll
                for (int fn = 0; fn < 8; fn++) {
                    uint32_t b0 = (fn & 1) ? bk[fn >> 1][1] : bk[fn >> 1][0];
                    uint32_t b1 = (fn & 1) ? bk[fn >> 1][3] : bk[fn >> 1][2];
                    mma16816(s[fm][fn], af[fm], b0, b1);
                }
        }

        #pragma unroll
        for (int fm = 0; fm < 2; fm++) {
            const int r0 = m0 + wq * 32 + fm * 16 + g;
            const int r1 = r0 + 8;
            float mx0 = NEG, mx1 = NEG;
            #pragma unroll
            for (int fn = 0; fn < 8; fn++) {
                const int cb = j0 + fn * 8 + tg * 2;
                float v0 = (cb     <= r0) ? s[fm][fn][0] * scale : NEG;
                float v1 = (cb + 1 <= r0) ? s[fm][fn][1] * scale : NEG;
                float v2 = (cb     <= r1) ? s[fm][fn][2] * scale : NEG;
                float v3 = (cb + 1 <= r1) ? s[fm][fn][3] * scale : NEG;
                s[fm][fn][0] = v0; s[fm][fn][1] = v1;
                s[fm][fn][2] = v2; s[fm][fn][3] = v3;
                mx0 = fmaxf(mx0, fmaxf(v0, v1));
                mx1 = fmaxf(mx1, fmaxf(v2, v3));
            }
            mx0 = fmaxf(mx0, __shfl_xor_sync(0xffffffffu, mx0, 1));
            mx0 = fmaxf(mx0, __shfl_xor_sync(0xffffffffu, mx0, 2));
            mx1 = fmaxf(mx1, __shfl_xor_sync(0xffffffffu, mx1, 1));
            mx1 = fmaxf(mx1, __shfl_xor_sync(0xffffffffu, mx1, 2));
            const float mn0 = fmaxf(mrow[fm][0], mx0);
            const float mn1 = fmaxf(mrow[fm][1], mx1);
            const float c0 = __expf(mrow[fm][0] - mn0);
            const float c1 = __expf(mrow[fm][1] - mn1);
            mrow[fm][0] = mn0; mrow[fm][1] = mn1;
            float ls0 = 0.f, ls1 = 0.f;
            #pragma unroll
            for (int fn = 0; fn < 8; fn++) {
                float p0 = __expf(s[fm][fn][0] - mn0);
                float p1 = __expf(s[fm][fn][1] - mn0);
                float p2 = __expf(s[fm][fn][2] - mn1);
                float p3 = __expf(s[fm][fn][3] - mn1);
                s[fm][fn][0] = p0; s[fm][fn][1] = p1;
                s[fm][fn][2] = p2; s[fm][fn][3] = p3;
                ls0 += p0 + p1; ls1 += p2 + p3;
                o[fm][fn][0] *= c0; o[fm][fn][1] *= c0;
                o[fm][fn][2] *= c1; o[fm][fn][3] *= c1;
            }
            lacc[fm][0] = lacc[fm][0] * c0 + ls0;
            lacc[fm][1] = lacc[fm][1] * c1 + ls1;
        }

        #pragma unroll
        for (int kc2 = 0; kc2 < 4; kc2++) {
            uint32_t aPh[2][4], aPl[2][4];
            #pragma unroll
            for (int fm = 0; fm < 2; fm++) {
                #pragma unroll
                for (int half = 0; half < 2; half++) {
                    const int fr = 2 * kc2 + half;
                    float p0 = s[fm][fr][0], p1 = s[fm][fr][1];
                    float p2 = s[fm][fr][2], p3 = s[fm][fr][3];
                    __half h0 = __float2half(p0), h1 = __float2half(p1);
                    __half h2 = __float2half(p2), h3 = __float2half(p3);
                    aPh[fm][half * 2 + 0] = pack_h2(h0, h1);
                    aPh[fm][half * 2 + 1] = pack_h2(h2, h3);
                    aPl[fm][half * 2 + 0] = pack_h2(
                        __float2half(p0 - __half2float(h0)),
                        __float2half(p1 - __half2float(h1)));
                    aPl[fm][half * 2 + 1] = pack_h2(
                        __float2half(p2 - __half2float(h2)),
                        __float2half(p3 - __half2float(h3)));
                }
            }
            uint32_t bv[4][4];
            #pragma unroll
            for (int fp = 0; fp < 4; fp++)
                ldmatrix_x4(bv[fp][0], bv[fp][1], bv[fp][2], bv[fp][3],
                    VsA + (uint32_t)((fp * 16 + lrow) * KVPAD + kc2 * 16 + lcol) * 2);
            #pragma unroll
            for (int fm = 0; fm < 2; fm++)
                #pragma unroll
                for (int fn = 0; fn < 8; fn++) {
                    uint32_t b0 = (fn & 1) ? bv[fn >> 1][1] : bv[fn >> 1][0];
                    uint32_t b1 = (fn & 1) ? bv[fn >> 1][3] : bv[fn >> 1][2];
                    mma16816(o[fm][fn], aPh[fm], b0, b1);
                    mma16816(o[fm][fn], aPl[fm], b0, b1);
                }
        }
    }

    float linv[2][2];
    #pragma unroll
    for (int fm = 0; fm < 2; fm++)
        #pragma unroll
        for (int half = 0; half < 2; half++) {
            float lv = lacc[fm][half];
            lv += __shfl_xor_sync(0xffffffffu, lv, 1);
            lv += __shfl_xor_sync(0xffffffffu, lv, 2);
            linv[fm][half] = 1.0f / lv;
        }
    #pragma unroll
    for (int fm = 0; fm < 2; fm++) {
        const int r0 = m0 + wq * 32 + fm * 16 + g;
        #pragma unroll
        for (int fn = 0; fn < 8; fn++) {
            const int col = h * HD + fn * 8 + tg * 2;
            float y0 = o[fm][fn][0] * linv[fm][0];
            float y1 = o[fm][fn][1] * linv[fm][0];
            float y2 = o[fm][fn][2] * linv[fm][1];
            float y3 = o[fm][fn][3] * linv[fm][1];
            __half h0 = __float2half(y0), h1 = __float2half(y1);
            __half h2 = __float2half(y2), h3 = __float2half(y3);
            size_t b0 = (size_t)r0 * KA2 + col;
            size_t b8 = b0 + 8 * KA2;
            *reinterpret_cast<uint32_t*>(A2o + b0) = pack_h2(h0, h1);
            *reinterpret_cast<uint32_t*>(A2o + b8) = pack_h2(h2, h3);
            *reinterpret_cast<uint32_t*>(A2o + b0 + KDIM) = pack_h2(
                __float2half(y0 - __half2float(h0)),
                __float2half(y1 - __half2float(h1)));
            *reinterpret_cast<uint32_t*>(A2o + b8 + KDIM) = pack_h2(
                __float2half(y2 - __half2float(h2)),
                __float2half(y3 - __half2float(h3)));
        }
    }
}

// ---------------------------------------------------------------------------
// Launch
// ---------------------------------------------------------------------------
extern "C" void kernel_launch(void* const* d_in, const int* in_sizes, int n_in,
                              void* d_out, int out_size)
{
    const float *q_embs, *k_embs, *v_embs, *w_q, *w_k, *w_v, *w_o;
    if (in_sizes[3] == D_MODEL * DIM_KV) {
        k_embs = (const float*)d_in[0];
        q_embs = (const float*)d_in[1];
        v_embs = (const float*)d_in[2];
        w_k    = (const float*)d_in[3];
        w_o    = (const float*)d_in[4];
        w_q    = (const float*)d_in[5];
        w_v    = (const float*)d_in[6];
    } else {
        q_embs = (const float*)d_in[0];
        k_embs = (const float*)d_in[1];
        v_embs = (const float*)d_in[2];
        w_q    = (const float*)d_in[3];
        w_k    = (const float*)d_in[4];
        w_v    = (const float*)d_in[5];
        w_o    = (const float*)d_in[6];
    }
    float* out = (float*)d_out;

    float *RC, *RS;
    __half *A2q, *A2k, *A2v, *A2o, *B2q, *B2k, *B2v, *B2o, *Q2, *K2h, *Vth;
    cudaGetSymbolAddress((void**)&A2q, g_A2q);
    cudaGetSymbolAddress((void**)&A2k, g_A2k);
    cudaGetSymbolAddress((void**)&A2v, g_A2v);
    cudaGetSymbolAddress((void**)&A2o, g_A2o);
    cudaGetSymbolAddress((void**)&B2q, g_B2q);
    cudaGetSymbolAddress((void**)&B2k, g_B2k);
    cudaGetSymbolAddress((void**)&B2v, g_B2v);
    cudaGetSymbolAddress((void**)&B2o, g_B2o);
    cudaGetSymbolAddress((void**)&Q2,  g_Q2);
    cudaGetSymbolAddress((void**)&K2h, g_K2h);
    cudaGetSymbolAddress((void**)&Vth, g_Vth);
    cudaGetSymbolAddress((void**)&RC,  g_rc);
    cudaGetSymbolAddress((void**)&RS,  g_rs);

    cudaFuncSetAttribute(gemm_hmma_kernel<0>,
                         cudaFuncAttributeMaxDynamicSharedMemorySize, GEMM_SMEM_BYTES);
    cudaFuncSetAttribute(gemm_hmma_kernel<1>,
                         cudaFuncAttributeMaxDynamicSharedMemorySize, GEMM_SMEM_BYTES);
    cudaFuncSetAttribute(gemm_kv_kernel,
                         cudaFuncAttributeMaxDynamicSharedMemorySize, GEMM_SMEM_BYTES);
    cudaFuncSetAttribute(flash_hmma_kernel,
                         cudaFuncAttributeMaxDynamicSharedMemorySize, FLASH_SMEM_BYTES);

    const int M = T_SEQ;
    const int convA_blocks = (M * KDIM + 255) / 256;

    rope_table_kernel<<<(T_SEQ * 32 + 255) / 256, 256>>>(RC, RS);                        // 1
    split_a_kernel<<<convA_blocks, 256>>>(q_embs, A2q, M);                               // 2
    split_b_kernel<<<dim3(D_MODEL / 32, KDIM / 32), dim3(32, 8)>>>(w_q, B2q, D_MODEL);   // 3
    gemm_hmma_kernel<1><<<dim3(D_MODEL / 128, M / 128), 128, GEMM_SMEM_BYTES>>>(
        A2q, B2q, nullptr, Q2, D_MODEL, RC, RS);                                         // 4 (profile slot)

    split_a_kernel<<<convA_blocks, 256>>>(k_embs, A2k, M);
    split_b_kernel<<<dim3(DIM_KV / 32, KDIM / 32), dim3(32, 8)>>>(w_k, B2k, DIM_KV);
    split_a_kernel<<<convA_blocks, 256>>>(v_embs, A2v, M);
    split_b_kernel<<<dim3(DIM_KV / 32, KDIM / 32), dim3(32, 8)>>>(w_v, B2v, DIM_KV);

    // merged K+V projection: 128 CTAs, one per SM
    gemm_kv_kernel<<<dim3(DIM_KV / 128, M / 128, 2), 128, GEMM_SMEM_BYTES>>>(
        A2k, B2k, A2v, B2v, K2h, Vth, RC, RS);

    flash_hmma_kernel<<<dim3(T_SEQ / 128, NQH), 128, FLASH_SMEM_BYTES>>>(
        Q2, K2h, Vth, A2o);

    split_b_kernel<<<dim3(D_MODEL / 32, KDIM / 32), dim3(32, 8)>>>(w_o, B2o, D_MODEL);
    gemm_hmma_kernel<0><<<dim3(D_MODEL / 128, M / 128), 128, GEMM_SMEM_BYTES>>>(
        A2o, B2o, out, nullptr, D_MODEL, RC, RS);
}